// round 1
// baseline (speedup 1.0000x reference)
#include <cuda_runtime.h>
#include <cstdint>

#define N_NODES 100000
#define N_EDGES 1600000
#define C       128
#define C4      32          // C/4 float4 per row
#define BN      16          // nodes per GEMM block

// ---------------- scratch (device globals; no allocation allowed) ----------------
__device__ float4 g_agg[(size_t)N_NODES * C4];   // 51.2 MB aggregation buffer
__device__ float  g_cnt[N_NODES];                // per-node in-degree (float)
__device__ float4 g_h1 [(size_t)N_NODES * C4];   // layer-1 output
__device__ float4 g_h2 [(size_t)N_NODES * C4];   // layer-2 output

// ---------------- zero agg (+ counts on first layer) ----------------
__global__ void k_zero(int with_cnt) {
    int i = blockIdx.x * blockDim.x + threadIdx.x;
    int stride = gridDim.x * blockDim.x;
    const float4 z = make_float4(0.f, 0.f, 0.f, 0.f);
    for (int j = i; j < N_NODES * C4; j += stride) g_agg[j] = z;
    if (with_cnt)
        for (int j = i; j < N_NODES; j += stride) g_cnt[j] = 0.f;
}

// ---------------- edge scatter: agg[dst] += h[src], cnt[dst] += 1 ----------------
// one thread per (edge, 4-channel chunk): 1.6M * 32 threads, vector red.add
__global__ void k_scatter(const float4* __restrict__ h_ext,   // null -> g_h1
                          const int* __restrict__ ei,         // [2, E]
                          int do_cnt) {
    const float4* __restrict__ h = h_ext ? h_ext : (const float4*)g_h1;
    int i = blockIdx.x * blockDim.x + threadIdx.x;
    if (i >= N_EDGES * C4) return;
    int e  = i >> 5;
    int c4 = i & 31;
    int s = ei[e];
    int d = ei[N_EDGES + e];
    float4 v = __ldg(h + (size_t)s * C4 + c4);
    float4* p = g_agg + (size_t)d * C4 + c4;
    asm volatile("red.global.add.v4.f32 [%0], {%1,%2,%3,%4};"
                 :: "l"(p), "f"(v.x), "f"(v.y), "f"(v.z), "f"(v.w)
                 : "memory");
    if (do_cnt && c4 == 0) atomicAdd(g_cnt + d, 1.0f);
}

// ---------------- fused SAGE layer GEMM ----------------
// out[n,c] = relu( (agg[n,:]/max(cnt,1)) @ Wl + b + X[n,:] @ Wr )
// block = 128 threads (thread owns column c = tid), BN=16 nodes per block
__global__ void __launch_bounds__(128)
k_sage_gemm(const float4* __restrict__ Xext,   // null -> g_h1
            const float* __restrict__ Wl,
            const float* __restrict__ Wr,
            const float* __restrict__ bias,
            int out_sel)                       // 0 -> g_h1, 1 -> g_h2
{
    const float4* __restrict__ X = Xext ? Xext : (const float4*)g_h1;
    float* out = out_sel ? (float*)g_h2 : (float*)g_h1;

    __shared__ float sM[BN][C];   // mean tile
    __shared__ float sX[BN][C];   // self tile

    int tid  = threadIdx.x;       // 0..127 = output column
    int base = blockIdx.x * BN;

    // load tiles (thread tid loads channel tid of each node)
    #pragma unroll 4
    for (int n = 0; n < BN; n++) {
        int node = base + n;
        if (node < N_NODES) {
            float inv = 1.0f / fmaxf(g_cnt[node], 1.0f);
            sM[n][tid] = ((const float*)g_agg)[(size_t)node * C + tid] * inv;
            sX[n][tid] = ((const float*)X)[(size_t)node * C + tid];
        } else {
            sM[n][tid] = 0.f; sX[n][tid] = 0.f;
        }
    }
    __syncthreads();

    float acc[BN];
    float b = __ldg(bias + tid);
    #pragma unroll
    for (int n = 0; n < BN; n++) acc[n] = b;

    #pragma unroll 4
    for (int k0 = 0; k0 < C; k0 += 4) {
        float wl0 = __ldg(Wl + (k0 + 0) * C + tid);
        float wl1 = __ldg(Wl + (k0 + 1) * C + tid);
        float wl2 = __ldg(Wl + (k0 + 2) * C + tid);
        float wl3 = __ldg(Wl + (k0 + 3) * C + tid);
        float wr0 = __ldg(Wr + (k0 + 0) * C + tid);
        float wr1 = __ldg(Wr + (k0 + 1) * C + tid);
        float wr2 = __ldg(Wr + (k0 + 2) * C + tid);
        float wr3 = __ldg(Wr + (k0 + 3) * C + tid);
        #pragma unroll
        for (int n = 0; n < BN; n++) {
            float4 m  = *(const float4*)&sM[n][k0];
            float4 xv = *(const float4*)&sX[n][k0];
            acc[n] += m.x * wl0 + m.y * wl1 + m.z * wl2 + m.w * wl3
                    + xv.x * wr0 + xv.y * wr1 + xv.z * wr2 + xv.w * wr3;
        }
    }

    #pragma unroll
    for (int n = 0; n < BN; n++) {
        int node = base + n;
        if (node < N_NODES)
            out[(size_t)node * C + tid] = fmaxf(acc[n], 0.f);
    }
}

// ---------------- decoder + residual ----------------
// out[n,c] = alpha*(h2[n,:] @ Wd + bd)[c] + (1-alpha)*x[n,c]
__global__ void __launch_bounds__(128)
k_decoder(const float* __restrict__ x,
          const float* __restrict__ Wd,
          const float* __restrict__ bd,
          const float* __restrict__ alphaPtr,
          float* __restrict__ out)
{
    __shared__ float sH[BN][C];
    int tid  = threadIdx.x;
    int base = blockIdx.x * BN;
    float alpha = __ldg(alphaPtr);

    #pragma unroll 4
    for (int n = 0; n < BN; n++) {
        int node = base + n;
        sH[n][tid] = (node < N_NODES) ? ((const float*)g_h2)[(size_t)node * C + tid] : 0.f;
    }
    __syncthreads();

    float acc[BN];
    float b = __ldg(bd + tid);
    #pragma unroll
    for (int n = 0; n < BN; n++) acc[n] = b;

    #pragma unroll 4
    for (int k0 = 0; k0 < C; k0 += 4) {
        float w0 = __ldg(Wd + (k0 + 0) * C + tid);
        float w1 = __ldg(Wd + (k0 + 1) * C + tid);
        float w2 = __ldg(Wd + (k0 + 2) * C + tid);
        float w3 = __ldg(Wd + (k0 + 3) * C + tid);
        #pragma unroll
        for (int n = 0; n < BN; n++) {
            float4 h = *(const float4*)&sH[n][k0];
            acc[n] += h.x * w0 + h.y * w1 + h.z * w2 + h.w * w3;
        }
    }

    #pragma unroll
    for (int n = 0; n < BN; n++) {
        int node = base + n;
        if (node < N_NODES) {
            float xv = __ldg(x + (size_t)node * C + tid);
            out[(size_t)node * C + tid] = alpha * acc[n] + (1.0f - alpha) * xv;
        }
    }
}

// ---------------- launch ----------------
extern "C" void kernel_launch(void* const* d_in, const int* in_sizes, int n_in,
                              void* d_out, int out_size) {
    const float4* x   = (const float4*)d_in[0];
    const int*    ei  = (const int*)  d_in[1];
    const float*  W1l = (const float*)d_in[2];
    const float*  b1  = (const float*)d_in[3];
    const float*  W1r = (const float*)d_in[4];
    const float*  W2l = (const float*)d_in[5];
    const float*  b2  = (const float*)d_in[6];
    const float*  W2r = (const float*)d_in[7];
    const float*  Wd  = (const float*)d_in[8];
    const float*  bd  = (const float*)d_in[9];
    const float*  alp = (const float*)d_in[10];
    float* out = (float*)d_out;

    const int zeroBlocks    = 1024;
    const int scatterThreads = N_EDGES * C4;               // 51.2M
    const int scatterBlocks  = (scatterThreads + 255) / 256;
    const int gemmBlocks     = (N_NODES + BN - 1) / BN;    // 6250

    // Layer 1
    k_zero<<<zeroBlocks, 256>>>(1);
    k_scatter<<<scatterBlocks, 256>>>(x, ei, 1);
    k_sage_gemm<<<gemmBlocks, 128>>>(x, W1l, W1r, b1, /*out=h1*/0);

    // Layer 2
    k_zero<<<zeroBlocks, 256>>>(0);
    k_scatter<<<scatterBlocks, 256>>>(nullptr, ei, 0);
    k_sage_gemm<<<gemmBlocks, 128>>>(nullptr, W2l, W2r, b2, /*out=h2*/1);

    // Decoder + residual
    k_decoder<<<gemmBlocks, 128>>>((const float*)x, Wd, bd, alp, out);
}

// round 5
// speedup vs baseline: 1.6559x; 1.6559x over previous
#include <cuda_runtime.h>
#include <cstdint>

#define N_NODES 100000
#define N_EDGES 1600000
#define C       128
#define C4      32
#define BM      128          // rows per mma block
#define KC      32           // k-chunk
#define SA_STR  36           // sA row stride (floats)
#define SB_STR  136          // sB row stride (floats)

// ---------------- scratch ----------------
__device__ float4 g_agg[(size_t)N_NODES * C4];
__device__ float  g_cnt[N_NODES];
__device__ float4 g_h1 [(size_t)N_NODES * C4];
__device__ float4 g_h2 [(size_t)N_NODES * C4];

// ---------------- helpers ----------------
__device__ __forceinline__ float to_tf32(float x) {
    uint32_t u;
    asm("cvt.rna.tf32.f32 %0, %1;" : "=r"(u) : "f"(x));
    return __uint_as_float(u);
}
__device__ __forceinline__ void mma8(float* c,
                                     uint32_t a0, uint32_t a1, uint32_t a2, uint32_t a3,
                                     uint32_t b0, uint32_t b1) {
    asm volatile("mma.sync.aligned.m16n8k8.row.col.f32.tf32.tf32.f32 "
                 "{%0,%1,%2,%3}, {%4,%5,%6,%7}, {%8,%9}, {%0,%1,%2,%3};"
                 : "+f"(c[0]), "+f"(c[1]), "+f"(c[2]), "+f"(c[3])
                 : "r"(a0), "r"(a1), "r"(a2), "r"(a3), "r"(b0), "r"(b1));
}

// ---------------- zero agg (+ counts on first layer) ----------------
__global__ void k_zero(int with_cnt) {
    int i = blockIdx.x * blockDim.x + threadIdx.x;
    int stride = gridDim.x * blockDim.x;
    const float4 z = make_float4(0.f, 0.f, 0.f, 0.f);
    for (int j = i; j < N_NODES * C4; j += stride) g_agg[j] = z;
    if (with_cnt)
        for (int j = i; j < N_NODES; j += stride) g_cnt[j] = 0.f;
}

// ---------------- edge scatter ----------------
__global__ void k_scatter(const float4* __restrict__ h_ext,
                          const int* __restrict__ ei,
                          int do_cnt) {
    const float4* __restrict__ h = h_ext ? h_ext : (const float4*)g_h1;
    int i = blockIdx.x * blockDim.x + threadIdx.x;
    if (i >= N_EDGES * C4) return;
    int e  = i >> 5;
    int c4 = i & 31;
    int s = ei[e];
    int d = ei[N_EDGES + e];
    float4 v = __ldg(h + (size_t)s * C4 + c4);
    float4* p = g_agg + (size_t)d * C4 + c4;
    asm volatile("red.global.add.v4.f32 [%0], {%1,%2,%3,%4};"
                 :: "l"(p), "f"(v.x), "f"(v.y), "f"(v.z), "f"(v.w)
                 : "memory");
    if (do_cnt && c4 == 0) atomicAdd(g_cnt + d, 1.0f);
}

// ---------------- fused SAGE layer GEMM (tf32 mma) ----------------
// out = relu( [mean | x] @ [Wl ; Wr] + b ),  K = 256 (8 chunks of 32)
__global__ void __launch_bounds__(256, 2)
k_layer_mma(const float* __restrict__ Xext,   // null -> g_h1
            const float* __restrict__ Wl,
            const float* __restrict__ Wr,
            const float* __restrict__ bias,
            int out_sel) {
    const float* __restrict__ X = Xext ? Xext : (const float*)g_h1;
    float* out = out_sel ? (float*)g_h2 : (float*)g_h1;

    __shared__ float sA[BM * SA_STR];
    __shared__ float sB[KC * SB_STR];

    int tid = threadIdx.x, wid = tid >> 5, lane = tid & 31;
    int rowbase = blockIdx.x * BM;

    float acc[16][4];
    #pragma unroll
    for (int t = 0; t < 16; t++) { acc[t][0]=0.f; acc[t][1]=0.f; acc[t][2]=0.f; acc[t][3]=0.f; }

    for (int kc = 0; kc < 8; kc++) {
        bool meanpart = kc < 4;
        // ---- load A tile: 128 rows x 32 k = 1024 float4, 4 per thread
        #pragma unroll
        for (int it = 0; it < 4; it++) {
            int f4 = tid + it * 256;          // 0..1023
            int r  = f4 >> 3;                 // row within tile
            int q  = f4 & 7;                  // float4 within k-chunk
            int row = rowbase + r;
            float4 v = make_float4(0.f, 0.f, 0.f, 0.f);
            if (row < N_NODES) {
                if (meanpart) {
                    v = g_agg[(size_t)row * C4 + kc * 8 + q];
                    float inv = 1.0f / fmaxf(g_cnt[row], 1.0f);
                    v.x *= inv; v.y *= inv; v.z *= inv; v.w *= inv;
                } else {
                    v = ((const float4*)X)[(size_t)row * C4 + (kc - 4) * 8 + q];
                }
            }
            float* d = sA + r * SA_STR + q * 4;
            d[0] = to_tf32(v.x); d[1] = to_tf32(v.y);
            d[2] = to_tf32(v.z); d[3] = to_tf32(v.w);
        }
        // ---- load B tile: 32 k x 128 n = 1024 float4, 4 per thread
        const float* Wsrc = meanpart ? Wl : Wr;
        int kw0 = (meanpart ? kc : kc - 4) * KC;
        #pragma unroll
        for (int it = 0; it < 4; it++) {
            int f4 = tid + it * 256;
            int k  = f4 >> 5;                 // k row (0..31)
            int q  = f4 & 31;                 // float4 in n
            float4 v = __ldg((const float4*)(Wsrc + (size_t)(kw0 + k) * C) + q);
            float* d = sB + k * SB_STR + q * 4;
            d[0] = to_tf32(v.x); d[1] = to_tf32(v.y);
            d[2] = to_tf32(v.z); d[3] = to_tf32(v.w);
        }
        __syncthreads();

        // ---- compute: warp wid owns rows [wid*16, wid*16+16)
        int r0 = wid * 16;
        #pragma unroll
        for (int ks = 0; ks < 4; ks++) {
            int k0 = ks * 8;
            int ar = r0 + (lane >> 2);
            int ac = k0 + (lane & 3);
            uint32_t a0 = __float_as_uint(sA[ar * SA_STR + ac]);
            uint32_t a1 = __float_as_uint(sA[(ar + 8) * SA_STR + ac]);
            uint32_t a2 = __float_as_uint(sA[ar * SA_STR + ac + 4]);
            uint32_t a3 = __float_as_uint(sA[(ar + 8) * SA_STR + ac + 4]);
            int bk = k0 + (lane & 3);
            int bn = lane >> 2;
            #pragma unroll
            for (int t = 0; t < 16; t++) {
                uint32_t b0 = __float_as_uint(sB[bk * SB_STR + t * 8 + bn]);
                uint32_t b1 = __float_as_uint(sB[(bk + 4) * SB_STR + t * 8 + bn]);
                mma8(acc[t], a0, a1, a2, a3, b0, b1);
            }
        }
        __syncthreads();
    }

    // ---- epilogue: bias + relu, float2 stores
    int rA = rowbase + wid * 16 + (lane >> 2);
    int rB = rA + 8;
    #pragma unroll
    for (int t = 0; t < 16; t++) {
        int cbase = t * 8 + (lane & 3) * 2;
        float2 b2 = __ldg((const float2*)(bias + cbase));
        if (rA < N_NODES) {
            float2 o; o.x = fmaxf(acc[t][0] + b2.x, 0.f);
                      o.y = fmaxf(acc[t][1] + b2.y, 0.f);
            *(float2*)(out + (size_t)rA * C + cbase) = o;
        }
        if (rB < N_NODES) {
            float2 o; o.x = fmaxf(acc[t][2] + b2.x, 0.f);
                      o.y = fmaxf(acc[t][3] + b2.y, 0.f);
            *(float2*)(out + (size_t)rB * C + cbase) = o;
        }
    }
}

// ---------------- decoder + residual (tf32 mma), K = 128 ----------------
__global__ void __launch_bounds__(256, 2)
k_dec_mma(const float* __restrict__ x,
          const float* __restrict__ Wd,
          const float* __restrict__ bd,
          const float* __restrict__ alphaPtr,
          float* __restrict__ out) {
    __shared__ float sA[BM * SA_STR];
    __shared__ float sB[KC * SB_STR];

    int tid = threadIdx.x, wid = tid >> 5, lane = tid & 31;
    int rowbase = blockIdx.x * BM;
    float alpha = __ldg(alphaPtr);
    float beta  = 1.0f - alpha;

    float acc[16][4];
    #pragma unroll
    for (int t = 0; t < 16; t++) { acc[t][0]=0.f; acc[t][1]=0.f; acc[t][2]=0.f; acc[t][3]=0.f; }

    for (int kc = 0; kc < 4; kc++) {
        #pragma unroll
        for (int it = 0; it < 4; it++) {
            int f4 = tid + it * 256;
            int r  = f4 >> 3;
            int q  = f4 & 7;
            int row = rowbase + r;
            float4 v = make_float4(0.f, 0.f, 0.f, 0.f);
            if (row < N_NODES)
                v = g_h2[(size_t)row * C4 + kc * 8 + q];
            float* d = sA + r * SA_STR + q * 4;
            d[0] = to_tf32(v.x); d[1] = to_tf32(v.y);
            d[2] = to_tf32(v.z); d[3] = to_tf32(v.w);
        }
        #pragma unroll
        for (int it = 0; it < 4; it++) {
            int f4 = tid + it * 256;
            int k  = f4 >> 5;
            int q  = f4 & 31;
            float4 v = __ldg((const float4*)(Wd + (size_t)(kc * KC + k) * C) + q);
            float* d = sB + k * SB_STR + q * 4;
            d[0] = to_tf32(v.x); d[1] = to_tf32(v.y);
            d[2] = to_tf32(v.z); d[3] = to_tf32(v.w);
        }
        __syncthreads();

        int r0 = wid * 16;
        #pragma unroll
        for (int ks = 0; ks < 4; ks++) {
            int k0 = ks * 8;
            int ar = r0 + (lane >> 2);
            int ac = k0 + (lane & 3);
            uint32_t a0 = __float_as_uint(sA[ar * SA_STR + ac]);
            uint32_t a1 = __float_as_uint(sA[(ar + 8) * SA_STR + ac]);
            uint32_t a2 = __float_as_uint(sA[ar * SA_STR + ac + 4]);
            uint32_t a3 = __float_as_uint(sA[(ar + 8) * SA_STR + ac + 4]);
            int bk = k0 + (lane & 3);
            int bn = lane >> 2;
            #pragma unroll
            for (int t = 0; t < 16; t++) {
                uint32_t b0 = __float_as_uint(sB[bk * SB_STR + t * 8 + bn]);
                uint32_t b1 = __float_as_uint(sB[(bk + 4) * SB_STR + t * 8 + bn]);
                mma8(acc[t], a0, a1, a2, a3, b0, b1);
            }
        }
        __syncthreads();
    }

    int rA = rowbase + wid * 16 + (lane >> 2);
    int rB = rA + 8;
    #pragma unroll
    for (int t = 0; t < 16; t++) {
        int cbase = t * 8 + (lane & 3) * 2;
        float2 b2 = __ldg((const float2*)(bd + cbase));
        if (rA < N_NODES) {
            float2 xv = __ldg((const float2*)(x + (size_t)rA * C + cbase));
            float2 o; o.x = alpha * (acc[t][0] + b2.x) + beta * xv.x;
                      o.y = alpha * (acc[t][1] + b2.y) + beta * xv.y;
            *(float2*)(out + (size_t)rA * C + cbase) = o;
        }
        if (rB < N_NODES) {
            float2 xv = __ldg((const float2*)(x + (size_t)rB * C + cbase));
            float2 o; o.x = alpha * (acc[t][2] + b2.x) + beta * xv.x;
                      o.y = alpha * (acc[t][3] + b2.y) + beta * xv.y;
            *(float2*)(out + (size_t)rB * C + cbase) = o;
        }
    }
}

// ---------------- launch ----------------
extern "C" void kernel_launch(void* const* d_in, const int* in_sizes, int n_in,
                              void* d_out, int out_size) {
    const float4* x   = (const float4*)d_in[0];
    const int*    ei  = (const int*)  d_in[1];
    const float*  W1l = (const float*)d_in[2];
    const float*  b1  = (const float*)d_in[3];
    const float*  W1r = (const float*)d_in[4];
    const float*  W2l = (const float*)d_in[5];
    const float*  b2  = (const float*)d_in[6];
    const float*  W2r = (const float*)d_in[7];
    const float*  Wd  = (const float*)d_in[8];
    const float*  bd  = (const float*)d_in[9];
    const float*  alp = (const float*)d_in[10];
    float* out = (float*)d_out;

    const int zeroBlocks     = 1024;
    const int scatterThreads = N_EDGES * C4;
    const int scatterBlocks  = (scatterThreads + 255) / 256;
    const int mmaBlocks      = (N_NODES + BM - 1) / BM;   // 782

    // Layer 1
    k_zero<<<zeroBlocks, 256>>>(1);
    k_scatter<<<scatterBlocks, 256>>>(x, ei, 1);
    k_layer_mma<<<mmaBlocks, 256>>>((const float*)x, W1l, W1r, b1, /*out=h1*/0);

    // Layer 2
    k_zero<<<zeroBlocks, 256>>>(0);
    k_scatter<<<scatterBlocks, 256>>>(nullptr, ei, 0);
    k_layer_mma<<<mmaBlocks, 256>>>(nullptr, W2l, W2r, b2, /*out=h2*/1);

    // Decoder + residual
    k_dec_mma<<<mmaBlocks, 256>>>((const float*)x, Wd, bd, alp, out);
}

// round 6
// speedup vs baseline: 2.6851x; 1.6215x over previous
#include <cuda_runtime.h>
#include <cstdint>

#define N_NODES 100000
#define N_EDGES 1600000
#define C       128
#define C4      32
#define BM      128
#define KC      32
#define SA_STR  36
#define SB_STR  136

// ---------------- scratch ----------------
__device__ float4 g_mean[(size_t)N_NODES * C4];   // mean-aggregated features
__device__ float4 g_h1 [(size_t)N_NODES * C4];
__device__ float4 g_h2 [(size_t)N_NODES * C4];
__device__ int    g_deg [N_NODES];
__device__ int    g_cur [N_NODES];
__device__ int    g_off [N_NODES + 1];
__device__ int    g_srcs[N_EDGES];

// ---------------- helpers ----------------
__device__ __forceinline__ float to_tf32(float x) {
    uint32_t u;
    asm("cvt.rna.tf32.f32 %0, %1;" : "=r"(u) : "f"(x));
    return __uint_as_float(u);
}
__device__ __forceinline__ void mma8(float* c,
                                     uint32_t a0, uint32_t a1, uint32_t a2, uint32_t a3,
                                     uint32_t b0, uint32_t b1) {
    asm volatile("mma.sync.aligned.m16n8k8.row.col.f32.tf32.tf32.f32 "
                 "{%0,%1,%2,%3}, {%4,%5,%6,%7}, {%8,%9}, {%0,%1,%2,%3};"
                 : "+f"(c[0]), "+f"(c[1]), "+f"(c[2]), "+f"(c[3])
                 : "r"(a0), "r"(a1), "r"(a2), "r"(a3), "r"(b0), "r"(b1));
}

// ================= CSR build =================
__global__ void k_csr_init() {
    int i = blockIdx.x * blockDim.x + threadIdx.x;
    int stride = gridDim.x * blockDim.x;
    for (int j = i; j < N_NODES; j += stride) { g_deg[j] = 0; g_cur[j] = 0; }
}

__global__ void k_hist(const int* __restrict__ ei) {
    int e = blockIdx.x * blockDim.x + threadIdx.x;
    if (e >= N_EDGES) return;
    atomicAdd(g_deg + ei[N_EDGES + e], 1);
}

// single-block exclusive scan of g_deg -> g_off, 4 elements/thread/iter
__global__ void __launch_bounds__(1024)
k_scan() {
    __shared__ int s_wsum[32];
    __shared__ int s_carry;
    int tid = threadIdx.x, lane = tid & 31, wid = tid >> 5;
    if (tid == 0) { s_carry = 0; g_off[0] = 0; }
    __syncthreads();

    for (int base = 0; base < N_NODES; base += 4096) {
        int i0 = base + tid * 4;
        int d0 = (i0 + 0 < N_NODES) ? g_deg[i0 + 0] : 0;
        int d1 = (i0 + 1 < N_NODES) ? g_deg[i0 + 1] : 0;
        int d2 = (i0 + 2 < N_NODES) ? g_deg[i0 + 2] : 0;
        int d3 = (i0 + 3 < N_NODES) ? g_deg[i0 + 3] : 0;
        int tot = d0 + d1 + d2 + d3;

        // warp inclusive scan of tot
        int s = tot;
        #pragma unroll
        for (int o = 1; o < 32; o <<= 1) {
            int t = __shfl_up_sync(0xffffffffu, s, o);
            if (lane >= o) s += t;
        }
        if (lane == 31) s_wsum[wid] = s;
        __syncthreads();
        if (wid == 0) {
            int w = s_wsum[lane];
            #pragma unroll
            for (int o = 1; o < 32; o <<= 1) {
                int t = __shfl_up_sync(0xffffffffu, w, o);
                if (lane >= o) w += t;
            }
            s_wsum[lane] = w;
        }
        __syncthreads();

        int excl = s_carry + (wid ? s_wsum[wid - 1] : 0) + s - tot;
        if (i0 + 0 < N_NODES) g_off[i0 + 1] = excl + d0;
        if (i0 + 1 < N_NODES) g_off[i0 + 2] = excl + d0 + d1;
        if (i0 + 2 < N_NODES) g_off[i0 + 3] = excl + d0 + d1 + d2;
        if (i0 + 3 < N_NODES) g_off[i0 + 4] = excl + tot;

        __syncthreads();
        if (tid == 0) s_carry += s_wsum[31];
        __syncthreads();
    }
}

__global__ void k_fill(const int* __restrict__ ei) {
    int e = blockIdx.x * blockDim.x + threadIdx.x;
    if (e >= N_EDGES) return;
    int srcv = ei[e];
    int d    = ei[N_EDGES + e];
    int pos  = atomicAdd(g_cur + d, 1);
    g_srcs[g_off[d] + pos] = srcv;
}

// ================= aggregation (gather) =================
// one warp per dst node; lane owns 4 channels; writes mean directly
__global__ void __launch_bounds__(256)
k_agg(const float4* __restrict__ h_ext) {   // null -> g_h1
    const float4* __restrict__ h = h_ext ? h_ext : (const float4*)g_h1;
    int node = (blockIdx.x * blockDim.x + threadIdx.x) >> 5;
    if (node >= N_NODES) return;
    int lane = threadIdx.x & 31;

    int beg = g_off[node];
    int end = g_off[node + 1];

    float4 a0 = make_float4(0.f, 0.f, 0.f, 0.f);
    float4 a1 = make_float4(0.f, 0.f, 0.f, 0.f);

    for (int j0 = beg; j0 < end; j0 += 32) {
        int myj  = j0 + lane;
        int s_my = (myj < end) ? __ldg(g_srcs + myj) : 0;
        int cnt  = min(32, end - j0);
        int t = 0;
        for (; t + 4 <= cnt; t += 4) {
            int s0 = __shfl_sync(0xffffffffu, s_my, t + 0);
            int s1 = __shfl_sync(0xffffffffu, s_my, t + 1);
            int s2 = __shfl_sync(0xffffffffu, s_my, t + 2);
            int s3 = __shfl_sync(0xffffffffu, s_my, t + 3);
            float4 v0 = __ldg(h + (size_t)s0 * C4 + lane);
            float4 v1 = __ldg(h + (size_t)s1 * C4 + lane);
            float4 v2 = __ldg(h + (size_t)s2 * C4 + lane);
            float4 v3 = __ldg(h + (size_t)s3 * C4 + lane);
            a0.x += v0.x; a0.y += v0.y; a0.z += v0.z; a0.w += v0.w;
            a1.x += v1.x; a1.y += v1.y; a1.z += v1.z; a1.w += v1.w;
            a0.x += v2.x; a0.y += v2.y; a0.z += v2.z; a0.w += v2.w;
            a1.x += v3.x; a1.y += v3.y; a1.z += v3.z; a1.w += v3.w;
        }
        for (; t < cnt; t++) {
            int s0 = __shfl_sync(0xffffffffu, s_my, t);
            float4 v0 = __ldg(h + (size_t)s0 * C4 + lane);
            a0.x += v0.x; a0.y += v0.y; a0.z += v0.z; a0.w += v0.w;
        }
    }

    float inv = 1.0f / fmaxf((float)(end - beg), 1.0f);
    float4 m;
    m.x = (a0.x + a1.x) * inv;
    m.y = (a0.y + a1.y) * inv;
    m.z = (a0.z + a1.z) * inv;
    m.w = (a0.w + a1.w) * inv;
    g_mean[(size_t)node * C4 + lane] = m;
}

// ================= fused SAGE layer GEMM (tf32 mma) =================
// out = relu( [mean | x] @ [Wl ; Wr] + b ),  K = 256 (8 chunks of 32)
__global__ void __launch_bounds__(256, 2)
k_layer_mma(const float* __restrict__ Xext,   // null -> g_h1
            const float* __restrict__ Wl,
            const float* __restrict__ Wr,
            const float* __restrict__ bias,
            int out_sel) {
    const float* __restrict__ X = Xext ? Xext : (const float*)g_h1;
    float* out = out_sel ? (float*)g_h2 : (float*)g_h1;

    __shared__ float sA[BM * SA_STR];
    __shared__ float sB[KC * SB_STR];

    int tid = threadIdx.x, wid = tid >> 5, lane = tid & 31;
    int rowbase = blockIdx.x * BM;

    float acc[16][4];
    #pragma unroll
    for (int t = 0; t < 16; t++) { acc[t][0]=0.f; acc[t][1]=0.f; acc[t][2]=0.f; acc[t][3]=0.f; }

    for (int kc = 0; kc < 8; kc++) {
        bool meanpart = kc < 4;
        #pragma unroll
        for (int it = 0; it < 4; it++) {
            int f4 = tid + it * 256;
            int r  = f4 >> 3;
            int q  = f4 & 7;
            int row = rowbase + r;
            float4 v = make_float4(0.f, 0.f, 0.f, 0.f);
            if (row < N_NODES) {
                if (meanpart) v = g_mean[(size_t)row * C4 + kc * 8 + q];
                else          v = ((const float4*)X)[(size_t)row * C4 + (kc - 4) * 8 + q];
            }
            float* d = sA + r * SA_STR + q * 4;
            d[0] = to_tf32(v.x); d[1] = to_tf32(v.y);
            d[2] = to_tf32(v.z); d[3] = to_tf32(v.w);
        }
        const float* Wsrc = meanpart ? Wl : Wr;
        int kw0 = (meanpart ? kc : kc - 4) * KC;
        #pragma unroll
        for (int it = 0; it < 4; it++) {
            int f4 = tid + it * 256;
            int k  = f4 >> 5;
            int q  = f4 & 31;
            float4 v = __ldg((const float4*)(Wsrc + (size_t)(kw0 + k) * C) + q);
            float* d = sB + k * SB_STR + q * 4;
            d[0] = to_tf32(v.x); d[1] = to_tf32(v.y);
            d[2] = to_tf32(v.z); d[3] = to_tf32(v.w);
        }
        __syncthreads();

        int r0 = wid * 16;
        #pragma unroll
        for (int ks = 0; ks < 4; ks++) {
            int k0 = ks * 8;
            int ar = r0 + (lane >> 2);
            int ac = k0 + (lane & 3);
            uint32_t a0 = __float_as_uint(sA[ar * SA_STR + ac]);
            uint32_t a1 = __float_as_uint(sA[(ar + 8) * SA_STR + ac]);
            uint32_t a2 = __float_as_uint(sA[ar * SA_STR + ac + 4]);
            uint32_t a3 = __float_as_uint(sA[(ar + 8) * SA_STR + ac + 4]);
            int bk = k0 + (lane & 3);
            int bn = lane >> 2;
            #pragma unroll
            for (int t = 0; t < 16; t++) {
                uint32_t b0 = __float_as_uint(sB[bk * SB_STR + t * 8 + bn]);
                uint32_t b1 = __float_as_uint(sB[(bk + 4) * SB_STR + t * 8 + bn]);
                mma8(acc[t], a0, a1, a2, a3, b0, b1);
            }
        }
        __syncthreads();
    }

    int rA = rowbase + wid * 16 + (lane >> 2);
    int rB = rA + 8;
    #pragma unroll
    for (int t = 0; t < 16; t++) {
        int cbase = t * 8 + (lane & 3) * 2;
        float2 b2 = __ldg((const float2*)(bias + cbase));
        if (rA < N_NODES) {
            float2 o; o.x = fmaxf(acc[t][0] + b2.x, 0.f);
                      o.y = fmaxf(acc[t][1] + b2.y, 0.f);
            *(float2*)(out + (size_t)rA * C + cbase) = o;
        }
        if (rB < N_NODES) {
            float2 o; o.x = fmaxf(acc[t][2] + b2.x, 0.f);
                      o.y = fmaxf(acc[t][3] + b2.y, 0.f);
            *(float2*)(out + (size_t)rB * C + cbase) = o;
        }
    }
}

// ================= decoder + residual (tf32 mma), K = 128 =================
__global__ void __launch_bounds__(256, 2)
k_dec_mma(const float* __restrict__ x,
          const float* __restrict__ Wd,
          const float* __restrict__ bd,
          const float* __restrict__ alphaPtr,
          float* __restrict__ out) {
    __shared__ float sA[BM * SA_STR];
    __shared__ float sB[KC * SB_STR];

    int tid = threadIdx.x, wid = tid >> 5, lane = tid & 31;
    int rowbase = blockIdx.x * BM;
    float alpha = __ldg(alphaPtr);
    float beta  = 1.0f - alpha;

    float acc[16][4];
    #pragma unroll
    for (int t = 0; t < 16; t++) { acc[t][0]=0.f; acc[t][1]=0.f; acc[t][2]=0.f; acc[t][3]=0.f; }

    for (int kc = 0; kc < 4; kc++) {
        #pragma unroll
        for (int it = 0; it < 4; it++) {
            int f4 = tid + it * 256;
            int r  = f4 >> 3;
            int q  = f4 & 7;
            int row = rowbase + r;
            float4 v = make_float4(0.f, 0.f, 0.f, 0.f);
            if (row < N_NODES)
                v = g_h2[(size_t)row * C4 + kc * 8 + q];
            float* d = sA + r * SA_STR + q * 4;
            d[0] = to_tf32(v.x); d[1] = to_tf32(v.y);
            d[2] = to_tf32(v.z); d[3] = to_tf32(v.w);
        }
        #pragma unroll
        for (int it = 0; it < 4; it++) {
            int f4 = tid + it * 256;
            int k  = f4 >> 5;
            int q  = f4 & 31;
            float4 v = __ldg((const float4*)(Wd + (size_t)(kc * KC + k) * C) + q);
            float* d = sB + k * SB_STR + q * 4;
            d[0] = to_tf32(v.x); d[1] = to_tf32(v.y);
            d[2] = to_tf32(v.z); d[3] = to_tf32(v.w);
        }
        __syncthreads();

        int r0 = wid * 16;
        #pragma unroll
        for (int ks = 0; ks < 4; ks++) {
            int k0 = ks * 8;
            int ar = r0 + (lane >> 2);
            int ac = k0 + (lane & 3);
            uint32_t a0 = __float_as_uint(sA[ar * SA_STR + ac]);
            uint32_t a1 = __float_as_uint(sA[(ar + 8) * SA_STR + ac]);
            uint32_t a2 = __float_as_uint(sA[ar * SA_STR + ac + 4]);
            uint32_t a3 = __float_as_uint(sA[(ar + 8) * SA_STR + ac + 4]);
            int bk = k0 + (lane & 3);
            int bn = lane >> 2;
            #pragma unroll
            for (int t = 0; t < 16; t++) {
                uint32_t b0 = __float_as_uint(sB[bk * SB_STR + t * 8 + bn]);
                uint32_t b1 = __float_as_uint(sB[(bk + 4) * SB_STR + t * 8 + bn]);
                mma8(acc[t], a0, a1, a2, a3, b0, b1);
            }
        }
        __syncthreads();
    }

    int rA = rowbase + wid * 16 + (lane >> 2);
    int rB = rA + 8;
    #pragma unroll
    for (int t = 0; t < 16; t++) {
        int cbase = t * 8 + (lane & 3) * 2;
        float2 b2 = __ldg((const float2*)(bd + cbase));
        if (rA < N_NODES) {
            float2 xv = __ldg((const float2*)(x + (size_t)rA * C + cbase));
            float2 o; o.x = alpha * (acc[t][0] + b2.x) + beta * xv.x;
                      o.y = alpha * (acc[t][1] + b2.y) + beta * xv.y;
            *(float2*)(out + (size_t)rA * C + cbase) = o;
        }
        if (rB < N_NODES) {
            float2 xv = __ldg((const float2*)(x + (size_t)rB * C + cbase));
            float2 o; o.x = alpha * (acc[t][2] + b2.x) + beta * xv.x;
                      o.y = alpha * (acc[t][3] + b2.y) + beta * xv.y;
            *(float2*)(out + (size_t)rB * C + cbase) = o;
        }
    }
}

// ================= launch =================
extern "C" void kernel_launch(void* const* d_in, const int* in_sizes, int n_in,
                              void* d_out, int out_size) {
    const float4* x   = (const float4*)d_in[0];
    const int*    ei  = (const int*)  d_in[1];
    const float*  W1l = (const float*)d_in[2];
    const float*  b1  = (const float*)d_in[3];
    const float*  W1r = (const float*)d_in[4];
    const float*  W2l = (const float*)d_in[5];
    const float*  b2  = (const float*)d_in[6];
    const float*  W2r = (const float*)d_in[7];
    const float*  Wd  = (const float*)d_in[8];
    const float*  bd  = (const float*)d_in[9];
    const float*  alp = (const float*)d_in[10];
    float* out = (float*)d_out;

    const int edgeBlocks = (N_EDGES + 255) / 256;
    const int aggBlocks  = (N_NODES * 32 + 255) / 256;    // warp per node
    const int mmaBlocks  = (N_NODES + BM - 1) / BM;       // 782

    // CSR build (once, reused by both layers)
    k_csr_init<<<256, 256>>>();
    k_hist<<<edgeBlocks, 256>>>(ei);
    k_scan<<<1, 1024>>>();
    k_fill<<<edgeBlocks, 256>>>(ei);

    // Layer 1
    k_agg<<<aggBlocks, 256>>>(x);
    k_layer_mma<<<mmaBlocks, 256>>>((const float*)x, W1l, W1r, b1, /*out=h1*/0);

    // Layer 2
    k_agg<<<aggBlocks, 256>>>(nullptr);
    k_layer_mma<<<mmaBlocks, 256>>>(nullptr, W2l, W2r, b2, /*out=h2*/1);

    // Decoder + residual
    k_dec_mma<<<mmaBlocks, 256>>>((const float*)x, Wd, bd, alp, out);
}